// round 16
// baseline (speedup 1.0000x reference)
#include <cuda_runtime.h>
#include <cuda_bf16.h>
#include <math.h>
#include <stdint.h>

// Problem constants: B=2, S=2048, D=1024, H=16, DH=64, INNER=1024
#define BB   2
#define SS   2048
#define DD   1024
#define HH   16
#define DHD  64
#define MROWS (BB * SS)   // 4096 token rows

// Scratch (static device globals -- no allocations allowed)
__device__ float         g_x  [(size_t)MROWS * DD];     // tf32-rounded x
__device__ __nv_bfloat16 g_qb [(size_t)MROWS * DD];     // q (normalized+scaled) bf16
__device__ __nv_bfloat16 g_kb [(size_t)MROWS * DD];     // k (normalized) bf16
__device__ float         g_kv [(size_t)MROWS * 2 * DD]; // v half used (raw fp32)
__device__ __nv_bfloat16 g_vTb[(size_t)BB * HH * DHD * SS]; // v^T bf16: [bh][d][s]
__device__ float         g_vs [(size_t)BB * HH * DHD];  // V column sums (fp32, exact)
__device__ float         g_o  [(size_t)MROWS * DD];     // attention out (tf32-rounded)
__device__ float         g_wq [(size_t)DD * DD];
__device__ float         g_wkv[(size_t)DD * 2 * DD];
__device__ float         g_wo [(size_t)DD * DD];

// ---------------------------------------------------------------------------
// helpers
// ---------------------------------------------------------------------------
__device__ __forceinline__ uint32_t smem_u32(const void* p) {
    uint32_t a;
    asm("{ .reg .u64 t; cvta.to.shared.u64 t, %1; cvt.u32.u64 %0, t; }" : "=r"(a) : "l"(p));
    return a;
}

__device__ __forceinline__ float tf32r(float x) {
    uint32_t u;
    asm("cvt.rna.tf32.f32 %0, %1;" : "=r"(u) : "f"(x));
    return __uint_as_float(u);
}

// pack two floats to bf16x2 bits (rne)
__device__ __forceinline__ uint32_t bf2pack(float lo, float hi) {
    __nv_bfloat162 v = __floats2bfloat162_rn(lo, hi);
    uint32_t u;
    memcpy(&u, &v, 4);
    return u;
}

__device__ __forceinline__ void cp16(uint32_t dst, const void* src) {
    asm volatile("cp.async.cg.shared.global [%0], [%1], 16;" :: "r"(dst), "l"(src));
}
__device__ __forceinline__ void cp_commit() {
    asm volatile("cp.async.commit_group;" ::: "memory");
}
__device__ __forceinline__ void cp_wait0() {
    asm volatile("cp.async.wait_group 0;" ::: "memory");
}
__device__ __forceinline__ void cp_wait1() {
    asm volatile("cp.async.wait_group 1;" ::: "memory");
}

__device__ __forceinline__ void mma_tf32(float* d, const uint32_t* a, const uint32_t* b) {
    asm volatile(
        "mma.sync.aligned.m16n8k8.row.col.f32.tf32.tf32.f32 "
        "{%0,%1,%2,%3}, {%4,%5,%6,%7}, {%8,%9}, {%0,%1,%2,%3};"
        : "+f"(d[0]), "+f"(d[1]), "+f"(d[2]), "+f"(d[3])
        : "r"(a[0]), "r"(a[1]), "r"(a[2]), "r"(a[3]), "r"(b[0]), "r"(b[1]));
}

__device__ __forceinline__ void mma_bf16(float* d, const uint32_t* a, const uint32_t* b) {
    asm volatile(
        "mma.sync.aligned.m16n8k16.row.col.f32.bf16.bf16.f32 "
        "{%0,%1,%2,%3}, {%4,%5,%6,%7}, {%8,%9}, {%0,%1,%2,%3};"
        : "+f"(d[0]), "+f"(d[1]), "+f"(d[2]), "+f"(d[3])
        : "r"(a[0]), "r"(a[1]), "r"(a[2]), "r"(a[3]), "r"(b[0]), "r"(b[1]));
}

// ldmatrix x4 (b16 granularity)
__device__ __forceinline__ void ldm_x4(uint32_t* r, uint32_t addr) {
    asm volatile("ldmatrix.sync.aligned.m8n8.x4.shared.b16 {%0,%1,%2,%3}, [%4];"
        : "=r"(r[0]), "=r"(r[1]), "=r"(r[2]), "=r"(r[3]) : "r"(addr));
}

// ---------------------------------------------------------------------------
// tf32 rounding kernels
// ---------------------------------------------------------------------------
__global__ void round_tf32(const float* __restrict__ in, float* __restrict__ out, int n4)
{
    int i = blockIdx.x * blockDim.x + threadIdx.x;
    if (i < n4) {
        float4 v = ((const float4*)in)[i];
        v.x = tf32r(v.x); v.y = tf32r(v.y); v.z = tf32r(v.z); v.w = tf32r(v.w);
        ((float4*)out)[i] = v;
    }
}

#define WQ4  (DD * DD / 4)
#define WKV4 (2 * DD * DD / 4)
// rounds all weights AND zeroes the V-sum accumulator for this replay
__global__ void round_w(const float* __restrict__ wq,  float* __restrict__ owq,
                        const float* __restrict__ wkv, float* __restrict__ owkv,
                        const float* __restrict__ wo,  float* __restrict__ owo,
                        float* __restrict__ vsum)
{
    int i = blockIdx.x * blockDim.x + threadIdx.x;
    if (i < BB * HH * DHD) vsum[i] = 0.f;
    const float4* src;
    float4* dst;
    int idx;
    if (i < WQ4)             { src = (const float4*)wq;  dst = (float4*)owq;  idx = i; }
    else if (i < WQ4 + WKV4) { src = (const float4*)wkv; dst = (float4*)owkv; idx = i - WQ4; }
    else                     { src = (const float4*)wo;  dst = (float4*)owo;  idx = i - WQ4 - WKV4; }
    float4 v = src[idx];
    v.x = tf32r(v.x); v.y = tf32r(v.y); v.z = tf32r(v.z); v.w = tf32r(v.w);
    dst[idx] = v;
}

// ---------------------------------------------------------------------------
// V transpose + column sums: g_vTb[bh][d][s] = bf16(v), g_vs[bh][d] += sum_s v
// ---------------------------------------------------------------------------
__global__ void transpose_v(const float* __restrict__ kv, __nv_bfloat16* __restrict__ vT,
                            float* __restrict__ vsum)
{
    __shared__ float t[32][33];
    const int s0 = blockIdx.x * 32;
    const int d0 = blockIdx.y * 32;
    const int bh = blockIdx.z;
    const int b  = bh >> 4, h = bh & 15;
    const int tx = threadIdx.x, ty = threadIdx.y;

    const float* src = kv + (size_t)(b * SS) * (2 * DD) + DD + h * DHD;
#pragma unroll
    for (int i = 0; i < 32; i += 8)
        t[ty + i][tx] = src[(size_t)(s0 + ty + i) * (2 * DD) + d0 + tx];
    __syncthreads();

    if (ty == 0) {
        float s = 0.f;
#pragma unroll
        for (int i = 0; i < 32; i++) s += t[i][tx];
        atomicAdd(&vsum[bh * DHD + d0 + tx], s);
    }

    __nv_bfloat16* dst = vT + ((size_t)bh * DHD + d0) * SS + s0;
#pragma unroll
    for (int i = 0; i < 32; i += 8)
        dst[(size_t)(ty + i) * SS + tx] = __float2bfloat16_rn(t[tx][ty + i]);
}

// ---------------------------------------------------------------------------
// Shared GEMM tile config -- 3-stage cp.async pipeline
// ---------------------------------------------------------------------------
#define GA_PITCH 36
#define GB_PITCH 136
#define GA_STG_F (128 * GA_PITCH)
#define GB_STG_F (32 * GB_PITCH)
#define GEMM_SMEM (3 * (GA_STG_F + GB_STG_F) * 4)   // 107520 B

// ---------------------------------------------------------------------------
// Fused qkv projection GEMM, 3-stage pipeline. Epilogue: q -> bf16
// (norm * exp(scale)); k -> bf16 (norm); v -> raw fp32.
// ---------------------------------------------------------------------------
__global__ __launch_bounds__(256) void mma_gemm_qkv(
    const float* __restrict__ A, const float* __restrict__ Wq,
    const float* __restrict__ Wkv, __nv_bfloat16* __restrict__ Qb,
    __nv_bfloat16* __restrict__ Kb, float* __restrict__ Ckv,
    const float* __restrict__ scale)
{
    extern __shared__ float smem[];
    float* sBf = smem + 3 * GA_STG_F;
    const uint32_t sbase = smem_u32(smem);

    const int t    = threadIdx.x;
    const int wid  = t >> 5, lane = t & 31;
    const int g    = lane >> 2, tg = lane & 3;
    const int wm   = wid >> 1, wn = wid & 1;
    const int bm   = blockIdx.y * 128;
    const int bn   = blockIdx.x * 128;
    const int K    = DD;

    const bool isQ = (bn < DD);
    const float* Bg = isQ ? (Wq + bn) : (Wkv + (bn - DD));
    const int Nb = isQ ? DD : 2 * DD;
    const int cb = isQ ? bn : bn - DD;

    const float* Ag = A + (size_t)bm * K;

    const int arow = t >> 1,  acol = (t & 1) * 16;
    const int brow = t >> 3,  bcol = (t & 7) * 4;

    const uint32_t a_lm = (uint32_t)(((lane & 7) + 8 * ((lane >> 3) & 1)) * GA_PITCH * 4
                                     + (lane >> 4) * 16);

    const int nk = K / 32;

    auto loadStage = [&](int s, int kt) {
        uint32_t ad = sbase + (uint32_t)(s * GA_STG_F + arow * GA_PITCH + acol) * 4u;
        const float* as = Ag + (size_t)arow * K + kt * 32 + acol;
#pragma unroll
        for (int u = 0; u < 4; u++) cp16(ad + u * 16, as + u * 4);
        uint32_t bd = sbase + (uint32_t)((3 * GA_STG_F) + s * GB_STG_F + brow * GB_PITCH + bcol) * 4u;
        const float* bs = Bg + (size_t)(kt * 32 + brow) * Nb + bcol;
#pragma unroll
        for (int u = 0; u < 4; u++) cp16(bd + u * 128, bs + u * 32);
    };

    float acc[2][8][4];
#pragma unroll
    for (int i = 0; i < 2; i++)
#pragma unroll
        for (int j = 0; j < 8; j++)
#pragma unroll
            for (int c = 0; c < 4; c++) acc[i][j][c] = 0.f;

    loadStage(0, 0); cp_commit();
    loadStage(1, 1); cp_commit();

    for (int kt = 0; kt < nk; kt++) {
        if (kt + 1 < nk) cp_wait1(); else cp_wait0();
        __syncthreads();   // stage kt visible; all warps done with stage kt-1

        if (kt + 2 < nk) {
            loadStage((kt + 2) % 3, kt + 2);   // overwrites stage kt-1: safe
            cp_commit();
        }

        const int st = kt % 3;
        const uint32_t saA = sbase + (uint32_t)(st * GA_STG_F) * 4u
                           + (uint32_t)(wm * 32 * GA_PITCH) * 4u + a_lm;
        const float* sb = sBf + st * GB_STG_F;

#pragma unroll
        for (int ks = 0; ks < 4; ks++) {
            uint32_t a[2][4];
            ldm_x4(a[0], saA + ks * 32);
            ldm_x4(a[1], saA + 16 * GA_PITCH * 4 + ks * 32);
            uint32_t b[8][2];
#pragma unroll
            for (int j = 0; j < 8; j++) {
                const int col = wn * 64 + j * 8 + g;
                b[j][0] = __float_as_uint(sb[(ks * 8 + tg    ) * GB_PITCH + col]);
                b[j][1] = __float_as_uint(sb[(ks * 8 + tg + 4) * GB_PITCH + col]);
            }
#pragma unroll
            for (int i = 0; i < 2; i++)
#pragma unroll
                for (int j = 0; j < 8; j++)
                    mma_tf32(acc[i][j], a[i], b[j]);
        }
    }

    const int colBase = cb + wn * 64;
    const bool isK = (!isQ) && (colBase < DD);
    const bool doNorm = isQ || isK;

#pragma unroll
    for (int i = 0; i < 2; i++) {
        const int row = bm + wm * 32 + i * 16 + g;
        float f0 = 1.f, f1 = 1.f;
        if (doNorm) {
            float ss0 = 0.f, ss1 = 0.f;
#pragma unroll
            for (int j = 0; j < 8; j++) {
                ss0 += acc[i][j][0] * acc[i][j][0] + acc[i][j][1] * acc[i][j][1];
                ss1 += acc[i][j][2] * acc[i][j][2] + acc[i][j][3] * acc[i][j][3];
            }
            ss0 += __shfl_xor_sync(0xffffffffu, ss0, 1);
            ss0 += __shfl_xor_sync(0xffffffffu, ss0, 2);
            ss1 += __shfl_xor_sync(0xffffffffu, ss1, 1);
            ss1 += __shfl_xor_sync(0xffffffffu, ss1, 2);
            f0 = 1.f / fmaxf(sqrtf(ss0), 1e-12f);
            f1 = 1.f / fmaxf(sqrtf(ss1), 1e-12f);
            if (isQ) {
                const float e = expf(scale[colBase >> 6]);
                f0 *= e;
                f1 *= e;
            }
        }
#pragma unroll
        for (int j = 0; j < 8; j++) {
            const int col = colBase + j * 8 + tg * 2;
            if (doNorm) {
                __nv_bfloat16* dst = isQ ? Qb : Kb;
                __nv_bfloat162 v0 = __floats2bfloat162_rn(acc[i][j][0] * f0, acc[i][j][1] * f0);
                __nv_bfloat162 v1 = __floats2bfloat162_rn(acc[i][j][2] * f1, acc[i][j][3] * f1);
                *(__nv_bfloat162*)(dst + (size_t)row * DD + col)       = v0;
                *(__nv_bfloat162*)(dst + (size_t)(row + 8) * DD + col) = v1;
            } else {
                float2 v0 = make_float2(acc[i][j][0], acc[i][j][1]);
                float2 v1 = make_float2(acc[i][j][2], acc[i][j][3]);
                *(float2*)(Ckv + (size_t)row * Nb + col)       = v0;
                *(float2*)(Ckv + (size_t)(row + 8) * Nb + col) = v1;
            }
        }
    }
}

// ---------------------------------------------------------------------------
// Plain tf32 GEMM (out projection), 3-stage pipeline.
// ---------------------------------------------------------------------------
__global__ __launch_bounds__(256) void mma_gemm(
    const float* __restrict__ A, const float* __restrict__ B,
    float* __restrict__ C, int N, int K, const float* __restrict__ bias)
{
    extern __shared__ float smem[];
    float* sBf = smem + 3 * GA_STG_F;
    const uint32_t sbase = smem_u32(smem);

    const int t    = threadIdx.x;
    const int wid  = t >> 5, lane = t & 31;
    const int g    = lane >> 2, tg = lane & 3;
    const int wm   = wid >> 1, wn = wid & 1;
    const int bm   = blockIdx.y * 128;
    const int bn   = blockIdx.x * 128;

    const float* Ag = A + (size_t)bm * K;
    const float* Bg = B + bn;

    const int arow = t >> 1,  acol = (t & 1) * 16;
    const int brow = t >> 3,  bcol = (t & 7) * 4;

    const uint32_t a_lm = (uint32_t)(((lane & 7) + 8 * ((lane >> 3) & 1)) * GA_PITCH * 4
                                     + (lane >> 4) * 16);

    const int nk = K / 32;

    auto loadStage = [&](int s, int kt) {
        uint32_t ad = sbase + (uint32_t)(s * GA_STG_F + arow * GA_PITCH + acol) * 4u;
        const float* as = Ag + (size_t)arow * K + kt * 32 + acol;
#pragma unroll
        for (int u = 0; u < 4; u++) cp16(ad + u * 16, as + u * 4);
        uint32_t bd = sbase + (uint32_t)((3 * GA_STG_F) + s * GB_STG_F + brow * GB_PITCH + bcol) * 4u;
        const float* bs = Bg + (size_t)(kt * 32 + brow) * N + bcol;
#pragma unroll
        for (int u = 0; u < 4; u++) cp16(bd + u * 128, bs + u * 32);
    };

    float acc[2][8][4];
#pragma unroll
    for (int i = 0; i < 2; i++)
#pragma unroll
        for (int j = 0; j < 8; j++)
#pragma unroll
            for (int c = 0; c < 4; c++) acc[i][j][c] = 0.f;

    loadStage(0, 0); cp_commit();
    loadStage(1, 1); cp_commit();

    for (int kt = 0; kt < nk; kt++) {
        if (kt + 1 < nk) cp_wait1(); else cp_wait0();
        __syncthreads();

        if (kt + 2 < nk) {
            loadStage((kt + 2) % 3, kt + 2);
            cp_commit();
        }

        const int st = kt % 3;
        const uint32_t saA = sbase + (uint32_t)(st * GA_STG_F) * 4u
                           + (uint32_t)(wm * 32 * GA_PITCH) * 4u + a_lm;
        const float* sb = sBf + st * GB_STG_F;

#pragma unroll
        for (int ks = 0; ks < 4; ks++) {
            uint32_t a[2][4];
            ldm_x4(a[0], saA + ks * 32);
            ldm_x4(a[1], saA + 16 * GA_PITCH * 4 + ks * 32);
            uint32_t b[8][2];
#pragma unroll
            for (int j = 0; j < 8; j++) {
                const int col = wn * 64 + j * 8 + g;
                b[j][0] = __float_as_uint(sb[(ks * 8 + tg    ) * GB_PITCH + col]);
                b[j][1] = __float_as_uint(sb[(ks * 8 + tg + 4) * GB_PITCH + col]);
            }
#pragma unroll
            for (int i = 0; i < 2; i++)
#pragma unroll
                for (int j = 0; j < 8; j++)
                    mma_tf32(acc[i][j], a[i], b[j]);
        }
    }

#pragma unroll
    for (int i = 0; i < 2; i++) {
        const int row = bm + wm * 32 + i * 16 + g;
#pragma unroll
        for (int j = 0; j < 8; j++) {
            const int col = bn + wn * 64 + j * 8 + tg * 2;
            float b0 = bias[col], b1 = bias[col + 1];
            float2 v0 = make_float2(acc[i][j][0] + b0, acc[i][j][1] + b1);
            float2 v1 = make_float2(acc[i][j][2] + b0, acc[i][j][3] + b1);
            *(float2*)(C + (size_t)row * N + col)       = v0;
            *(float2*)(C + (size_t)(row + 8) * N + col) = v1;
        }
    }
}

// ---------------------------------------------------------------------------
// Flash attention v7: uniform-softmax decomposition (validated R14) with
// 3-stage cp.async K/vT pipeline.
// ---------------------------------------------------------------------------
#define FQ  128
#define FKT 64
#define QBP 72                       // bf16 pitch (144 B)
#define QB_BYTES (FQ * QBP * 2)      // 18432
#define KB_BYTES (FKT * QBP * 2)     // 9216 (K tile) ; vT tile same size
#define KV_STG_BYTES (2 * KB_BYTES)  // 18432
#define FLASH_SMEM (QB_BYTES + 3 * KV_STG_BYTES)   // 73728

__global__ __launch_bounds__(256, 2) void flash_mma(
    const __nv_bfloat16* __restrict__ qb, const __nv_bfloat16* __restrict__ kb,
    const __nv_bfloat16* __restrict__ vTb, const float* __restrict__ vsum,
    float* __restrict__ o)
{
    extern __shared__ float sm[];
    const uint32_t sbase = smem_u32(sm);
    const uint32_t stgBase = sbase + QB_BYTES;

    const int qt = blockIdx.x, h = blockIdx.y, b = blockIdx.z;
    const int tid = threadIdx.x, wid = tid >> 5, lane = tid & 31;
    const int g = lane >> 2, tg = lane & 3;
    const int m0 = wid * 16;
    const int bh = b * HH + h;

    const __nv_bfloat16* qbase = qb + ((size_t)(b * SS) + qt * FQ) * DD + h * DHD;
    const __nv_bfloat16* kbbase = kb + (size_t)(b * SS) * DD + h * DHD;
    const __nv_bfloat16* vtbase = vTb + (size_t)bh * DHD * SS;

    const int ksr = tid >> 2, ksc = (tid & 3) * 16;

    const uint32_t a_lmb = (uint32_t)(((lane & 7) + 8 * ((lane >> 3) & 1)) * (QBP * 2)
                                      + (lane >> 4) * 16);
    const uint32_t b_lmb = (uint32_t)((lane & 7) * (QBP * 2) + (lane >> 3) * 16);

    auto prefetchKV = [&](int s, int jt) {
        const __nv_bfloat16* krow = kbbase + (size_t)(jt * FKT + ksr) * DD + ksc;
        uint32_t kd = stgBase + (uint32_t)(s * KV_STG_BYTES + ksr * (QBP * 2) + ksc * 2);
        cp16(kd,      krow);
        cp16(kd + 16, krow + 8);
        const __nv_bfloat16* vrow = vtbase + (size_t)ksr * SS + jt * FKT + ksc;
        uint32_t vd = kd + KB_BYTES;
        cp16(vd,      vrow);
        cp16(vd + 16, vrow + 8);
    };

    prefetchKV(0, 0); cp_commit();
    prefetchKV(1, 1); cp_commit();

    // Stage Q bf16 (128 rows x 64 bf16), 2 thr/row x 64B
    {
        const int r = tid >> 1, c0 = (tid & 1) * 32;
        const uint4* src = (const uint4*)(qbase + (size_t)r * DD + c0);
        char* dst = (char*)sm + r * (QBP * 2) + c0 * 2;
#pragma unroll
        for (int u = 0; u < 4; u++) *((uint4*)dst + u) = src[u];
    }
    __syncthreads();

    const uint32_t qpAddr = sbase + (uint32_t)(m0 * (QBP * 2)) + a_lmb;
    uint32_t qa[4][4];
#pragma unroll
    for (int c = 0; c < 4; c++) ldm_x4(qa[c], qpAddr + c * 32);

    float L0 = 0.f, L1 = 0.f;
    float oacc[8][4];
#pragma unroll
    for (int j = 0; j < 8; j++)
#pragma unroll
        for (int c = 0; c < 4; c++) oacc[j][c] = 0.f;

    const int NT = SS / FKT;
    for (int jt = 0; jt < NT; jt++) {
        if (jt + 1 < NT) cp_wait1(); else cp_wait0();
        __syncthreads();   // stage jt visible; all warps done with stage jt-1

        if (jt + 2 < NT) {
            prefetchKV((jt + 2) % 3, jt + 2);   // overwrites stage jt-1: safe
            cp_commit();
        }

        const int st = jt % 3;
        const uint32_t ksAddr = stgBase + (uint32_t)(st * KV_STG_BYTES) + b_lmb;
        const uint32_t vtAddr = ksAddr + KB_BYTES;

        float rs0 = 0.f, rs1 = 0.f;

#pragma unroll
        for (int half = 0; half < 2; half++) {   // 32-key halves
            uint32_t pk[4][2];
#pragma unroll
            for (int jj = 0; jj < 4; jj++) {
                const int j = half * 4 + jj;
                float sacc[4] = {0.f, 0.f, 0.f, 0.f};
                uint32_t r0[4], r1[4];
                const uint32_t jb = ksAddr + (uint32_t)(j * 8 * (QBP * 2));
                ldm_x4(r0, jb);
                ldm_x4(r1, jb + 64);
                mma_bf16(sacc, qa[0], r0);
                mma_bf16(sacc, qa[1], r0 + 2);
                mma_bf16(sacc, qa[2], r1);
                mma_bf16(sacc, qa[3], r1 + 2);

                // t = exp(s) - 1  (|s| <= 0.0455; no max needed)
                float t0 = __expf(sacc[0]) - 1.f;
                float t1 = __expf(sacc[1]) - 1.f;
                float t2 = __expf(sacc[2]) - 1.f;
                float t3 = __expf(sacc[3]) - 1.f;
                rs0 += t0 + t1;
                rs1 += t2 + t3;
                pk[jj][0] = bf2pack(t0, t1);   // row g
                pk[jj][1] = bf2pack(t2, t3);   // row g+8
            }

            uint32_t aA[4] = { pk[0][0], pk[0][1], pk[1][0], pk[1][1] };
            uint32_t aB[4] = { pk[2][0], pk[2][1], pk[3][0], pk[3][1] };
#pragma unroll
            for (int ob = 0; ob < 8; ob++) {
                uint32_t r[4];
                ldm_x4(r, vtAddr + (uint32_t)(ob * 8 * (QBP * 2)) + half * 64);
                mma_bf16(oacc[ob], aA, r);
                mma_bf16(oacc[ob], aB, r + 2);
            }
        }

        rs0 += __shfl_xor_sync(0xffffffffu, rs0, 1);
        rs0 += __shfl_xor_sync(0xffffffffu, rs0, 2);
        rs1 += __shfl_xor_sync(0xffffffffu, rs1, 1);
        rs1 += __shfl_xor_sync(0xffffffffu, rs1, 2);
        L0 += rs0;
        L1 += rs1;
    }

    // Epilogue: out = (Vsum + correction) / (S + sum t), tf32-rounded
    float* obase = o + ((size_t)(b * SS) + qt * FQ) * DD + h * DHD;
    const float* vs = vsum + (size_t)bh * DHD;
    const float inv0 = 1.f / ((float)SS + L0);
    const float inv1 = 1.f / ((float)SS + L1);
#pragma unroll
    for (int j = 0; j < 8; j++) {
        const int col = j * 8 + 2 * tg;
        const float s0 = vs[col], s1 = vs[col + 1];
        *(float2*)(obase + (size_t)(m0 + g    ) * DD + col) =
            make_float2(tf32r((s0 + oacc[j][0]) * inv0), tf32r((s1 + oacc[j][1]) * inv0));
        *(float2*)(obase + (size_t)(m0 + g + 8) * DD + col) =
            make_float2(tf32r((s0 + oacc[j][2]) * inv1), tf32r((s1 + oacc[j][3]) * inv1));
    }
}

// ---------------------------------------------------------------------------
extern "C" void kernel_launch(void* const* d_in, const int* in_sizes, int n_in,
                              void* d_out, int out_size)
{
    const float* x     = (const float*)d_in[0];
    const float* w_q   = (const float*)d_in[1];
    const float* w_kv  = (const float*)d_in[2];
    const float* w_out = (const float*)d_in[3];
    const float* b_out = (const float*)d_in[4];
    const float* scale = (const float*)d_in[5];
    float* out = (float*)d_out;

    float *px, *pkv, *pvs, *po, *pwq, *pwkv, *pwo;
    __nv_bfloat16 *pqb, *pkb, *pvTb;
    cudaGetSymbolAddress((void**)&px,   g_x);
    cudaGetSymbolAddress((void**)&pqb,  g_qb);
    cudaGetSymbolAddress((void**)&pkb,  g_kb);
    cudaGetSymbolAddress((void**)&pkv,  g_kv);
    cudaGetSymbolAddress((void**)&pvTb, g_vTb);
    cudaGetSymbolAddress((void**)&pvs,  g_vs);
    cudaGetSymbolAddress((void**)&po,   g_o);
    cudaGetSymbolAddress((void**)&pwq,  g_wq);
    cudaGetSymbolAddress((void**)&pwkv, g_wkv);
    cudaGetSymbolAddress((void**)&pwo,  g_wo);

    cudaFuncSetAttribute(flash_mma, cudaFuncAttributeMaxDynamicSharedMemorySize, FLASH_SMEM);
    cudaFuncSetAttribute(mma_gemm, cudaFuncAttributeMaxDynamicSharedMemorySize, GEMM_SMEM);
    cudaFuncSetAttribute(mma_gemm_qkv, cudaFuncAttributeMaxDynamicSharedMemorySize, GEMM_SMEM);

    const int T = 256;
    // round x ; round weights + zero vsum
    round_tf32<<<(MROWS * DD / 4 + T - 1) / T, T>>>(x, px, MROWS * DD / 4);
    round_w<<<(WQ4 + WKV4 + WQ4 + T - 1) / T, T>>>(w_q, pwq, w_kv, pwkv, w_out, pwo, pvs);

    // fused q + kv projections (q,k -> bf16; v -> raw fp32)
    mma_gemm_qkv<<<dim3(3 * DD / 128, MROWS / 128), 256, GEMM_SMEM>>>(
        px, pwq, pwkv, pqb, pkb, pkv, scale);

    // v^T bf16 + exact column sums
    transpose_v<<<dim3(SS / 32, DHD / 32, BB * HH), dim3(32, 8)>>>(pkv, pvTb, pvs);

    // attention (uniform-softmax decomposed, all-bf16 tensor work)
    flash_mma<<<dim3(SS / FQ, HH, BB), 256, FLASH_SMEM>>>(pqb, pkb, pvTb, pvs, po);

    // out = g_o @ w_out + b_out
    mma_gemm<<<dim3(DD / 128, MROWS / 128), 256, GEMM_SMEM>>>(
        po, pwo, out, DD, DD, b_out);
}